// round 2
// baseline (speedup 1.0000x reference)
#include <cuda_runtime.h>

// Problem constants (fixed by the reference)
namespace {
constexpr int Bn   = 8;
constexpr int Np   = 16384;
constexpr int MC   = 2048;
constexpr int KNN  = 32;
constexpr int C1   = 64;    // layer1 out channels
constexpr int C2   = 128;   // layer2 out channels
constexpr int EMB  = 256;   // layer3 out channels
}

// Pre-transposed W2: [c][o] layout. 32 KB, read-only, shared by all CTAs ->
// L2/L1 resident. Static __device__ scratch (no allocation).
__device__ float g_W2T[C1 * C2];

__global__ void prep_transpose_w2(const float* __restrict__ W2) {
    int i = blockIdx.x * blockDim.x + threadIdx.x;   // 8192 threads
    if (i < C1 * C2) {
        int c = i >> 7;          // / C2
        int o = i & (C2 - 1);
        g_W2T[i] = W2[o * C1 + c];
    }
}

__global__ __launch_bounds__(256, 1)
void patch_embed_kernel(const float* __restrict__ xyz,
                        const float* __restrict__ centers,
                        const int*   __restrict__ idx_knn,
                        const float* __restrict__ W1,
                        const float* __restrict__ b1,
                        const float* __restrict__ b2,
                        const float* __restrict__ W3,
                        const float* __restrict__ b3,
                        float*       __restrict__ out)
{
    // ~26.4 KB static shared — no dynamic smem, no cudaFuncSetAttribute.
    __shared__ __align__(16) float h1T[C1 * KNN];   // [c][k]  8 KB
    __shared__ __align__(16) float h2T[C2 * KNN];   // [c][k] 16 KB
    __shared__ float sW1[C1 * 3];
    __shared__ float sB1[C1];
    __shared__ float sB2[C2];
    __shared__ float locx[KNN], locy[KNN], locz[KNN];

    const int t  = threadIdx.x;
    const int bm = blockIdx.x;          // b*MC + m
    const int b  = bm >> 11;            // / MC (MC = 2048)

    // ---- stage small weights + gather -------------------------------------
    if (t < 192) sW1[t] = W1[t];
    if (t < 64)  sB1[t] = b1[t];
    if (t < 128) sB2[t] = b2[t];
    if (t < KNN) {
        const int i = idx_knn[bm * KNN + t];
        const float* p = xyz + ((size_t)b * Np + i) * 3;
        locx[t] = p[0] - centers[bm * 3 + 0];
        locy[t] = p[1] - centers[bm * 3 + 1];
        locz[t] = p[2] - centers[bm * 3 + 2];
    }
    __syncthreads();

    // ---- layer 1: 3 -> 64, relu  (h1T[o][k]) ------------------------------
    #pragma unroll
    for (int j = 0; j < (C1 * KNN) / 256; ++j) {
        const int i = t + j * 256;
        const int k = i & (KNN - 1);
        const int o = i >> 5;
        float v = sB1[o];
        v = fmaf(sW1[o * 3 + 0], locx[k], v);
        v = fmaf(sW1[o * 3 + 1], locy[k], v);
        v = fmaf(sW1[o * 3 + 2], locz[k], v);
        h1T[o * KNN + k] = fmaxf(v, 0.f);
    }
    __syncthreads();

    // ---- layer 2: 64 -> 128, relu, 4o x 4k register tile ------------------
    // Weights come straight from g_W2T via LDG.128 (L1/L2 resident; only 32
    // distinct addresses per c-step across the CTA). FFMA-bound: 16 FFMA per
    // (LDS.128 + LDG.128) pair.
    {
        const int o0 = (t & 31) * 4;     // 32 o-tiles
        const int k0 = (t >> 5) * 4;     // 8 k-tiles
        float acc[4][4];                 // [o][k]
        #pragma unroll
        for (int i = 0; i < 4; ++i)
            #pragma unroll
            for (int j = 0; j < 4; ++j)
                acc[i][j] = sB2[o0 + i];

        #pragma unroll 8
        for (int c = 0; c < C1; ++c) {
            const float4 hv = *reinterpret_cast<const float4*>(&h1T[c * KNN + k0]);
            const float4 wv = __ldg(reinterpret_cast<const float4*>(&g_W2T[c * C2 + o0]));
            const float hk[4] = {hv.x, hv.y, hv.z, hv.w};
            const float wo[4] = {wv.x, wv.y, wv.z, wv.w};
            #pragma unroll
            for (int i = 0; i < 4; ++i)
                #pragma unroll
                for (int j = 0; j < 4; ++j)
                    acc[i][j] = fmaf(wo[i], hk[j], acc[i][j]);
        }

        #pragma unroll
        for (int i = 0; i < 4; ++i) {
            float4 v;
            v.x = fmaxf(acc[i][0], 0.f);
            v.y = fmaxf(acc[i][1], 0.f);
            v.z = fmaxf(acc[i][2], 0.f);
            v.w = fmaxf(acc[i][3], 0.f);
            *reinterpret_cast<float4*>(&h2T[(o0 + i) * KNN + k0]) = v;
        }
    }
    __syncthreads();

    // ---- layer 3: 128 -> 256 + max over k ---------------------------------
    {
        const int o = t;                       // one output channel per thread
        float w[C2];                           // W3 row in registers
        const float* W3r = W3 + o * C2;
        #pragma unroll
        for (int c = 0; c < C2; c += 4) {
            const float4 v = *reinterpret_cast<const float4*>(&W3r[c]);
            w[c] = v.x; w[c + 1] = v.y; w[c + 2] = v.z; w[c + 3] = v.w;
        }

        float mx = -3.402823466e38f;
        #pragma unroll 1
        for (int k0 = 0; k0 < KNN; k0 += 4) {
            float a0 = 0.f, a1 = 0.f, a2 = 0.f, a3 = 0.f;
            #pragma unroll
            for (int c = 0; c < C2; ++c) {
                // broadcast LDS.128: all lanes read the same 4-k quad
                const float4 hv = *reinterpret_cast<const float4*>(&h2T[c * KNN + k0]);
                a0 = fmaf(hv.x, w[c], a0);
                a1 = fmaf(hv.y, w[c], a1);
                a2 = fmaf(hv.z, w[c], a2);
                a3 = fmaf(hv.w, w[c], a3);
            }
            mx = fmaxf(mx, fmaxf(fmaxf(a0, a1), fmaxf(a2, a3)));
        }
        out[(size_t)bm * EMB + o] = mx + b3[o];
    }
}

extern "C" void kernel_launch(void* const* d_in, const int* in_sizes, int n_in,
                              void* d_out, int out_size)
{
    // metadata order: xyz, centers, idx_knn, W1, b1, W2, b2, W3, b3
    const float* xyz     = (const float*)d_in[0];
    const float* centers = (const float*)d_in[1];
    const int*   idx_knn = (const int*)  d_in[2];
    const float* W1      = (const float*)d_in[3];
    const float* b1      = (const float*)d_in[4];
    const float* W2      = (const float*)d_in[5];
    const float* b2      = (const float*)d_in[6];
    const float* W3      = (const float*)d_in[7];
    const float* b3      = (const float*)d_in[8];
    float* out = (float*)d_out;

    prep_transpose_w2<<<(C1 * C2 + 255) / 256, 256>>>(W2);
    patch_embed_kernel<<<Bn * MC, 256>>>(
        xyz, centers, idx_knn, W1, b1, b2, W3, b3, out);
}

// round 3
// speedup vs baseline: 1.8342x; 1.8342x over previous
#include <cuda_runtime.h>

// Problem constants (fixed by the reference)
namespace {
constexpr int Bn   = 8;
constexpr int Np   = 16384;
constexpr int MC   = 2048;
constexpr int KNN  = 32;
constexpr int C1   = 64;    // layer1 out channels
constexpr int C2   = 128;   // layer2 out channels
constexpr int EMB  = 256;   // layer3 out channels
}

// Pre-transposed weights ([c][o] layout) in __device__ globals (no allocation).
// Read-only, shared by all CTAs -> L2/L1 resident.
__device__ float g_W2T[C1 * C2];    //  32 KB
__device__ float g_W3T[C2 * EMB];   // 128 KB

__global__ void prep_transpose(const float* __restrict__ W2,
                               const float* __restrict__ W3) {
    int i = blockIdx.x * blockDim.x + threadIdx.x;
    if (i < C1 * C2) {                       // W2: (128,64) -> [c][o]
        int c = i >> 7;
        int o = i & (C2 - 1);
        g_W2T[i] = W2[o * C1 + c];
    }
    int j = i - C1 * C2;
    if (j >= 0 && j < C2 * EMB) {            // W3: (256,128) -> [c][o]
        int c = j >> 8;
        int o = j & (EMB - 1);
        g_W3T[j] = W3[o * C2 + c];
    }
}

__global__ __launch_bounds__(256, 2)
void patch_embed_kernel(const float* __restrict__ xyz,
                        const float* __restrict__ centers,
                        const int*   __restrict__ idx_knn,
                        const float* __restrict__ W1,
                        const float* __restrict__ b1,
                        const float* __restrict__ b2,
                        const float* __restrict__ b3,
                        float*       __restrict__ out)
{
    __shared__ __align__(16) float h1T[C1 * KNN];   // [c][k]  8 KB
    __shared__ __align__(16) float h2T[C2 * KNN];   // [c][k] 16 KB
    __shared__ float sW1[C1 * 3];
    __shared__ float sB1[C1];
    __shared__ float sB2[C2];
    __shared__ float locx[KNN], locy[KNN], locz[KNN];

    const int t  = threadIdx.x;
    const int bm = blockIdx.x;          // b*MC + m
    const int b  = bm >> 11;            // / MC (MC = 2048)

    // ---- stage small weights + gather -------------------------------------
    if (t < 192) sW1[t] = W1[t];
    if (t < 64)  sB1[t] = b1[t];
    if (t < 128) sB2[t] = b2[t];
    if (t < KNN) {
        const int i = idx_knn[bm * KNN + t];
        const float* p = xyz + ((size_t)b * Np + i) * 3;
        locx[t] = p[0] - centers[bm * 3 + 0];
        locy[t] = p[1] - centers[bm * 3 + 1];
        locz[t] = p[2] - centers[bm * 3 + 2];
    }
    __syncthreads();

    // ---- layer 1: 3 -> 64, relu  (h1T[o][k]) ------------------------------
    #pragma unroll
    for (int j = 0; j < (C1 * KNN) / 256; ++j) {
        const int i = t + j * 256;
        const int k = i & (KNN - 1);
        const int o = i >> 5;
        float v = sB1[o];
        v = fmaf(sW1[o * 3 + 0], locx[k], v);
        v = fmaf(sW1[o * 3 + 1], locy[k], v);
        v = fmaf(sW1[o * 3 + 2], locz[k], v);
        h1T[o * KNN + k] = fmaxf(v, 0.f);
    }
    __syncthreads();

    // ---- layer 2: 64 -> 128, relu, 4o x 4k register tile ------------------
    // 16 FFMA per (LDS.128 + LDG.128).
    {
        const int o0 = (t & 31) * 4;     // 32 o-tiles
        const int k0 = (t >> 5) * 4;     // 8 k-tiles
        float acc[4][4];                 // [o][k]
        #pragma unroll
        for (int i = 0; i < 4; ++i)
            #pragma unroll
            for (int j = 0; j < 4; ++j)
                acc[i][j] = sB2[o0 + i];

        #pragma unroll 8
        for (int c = 0; c < C1; ++c) {
            const float4 hv = *reinterpret_cast<const float4*>(&h1T[c * KNN + k0]);
            const float4 wv = __ldg(reinterpret_cast<const float4*>(&g_W2T[c * C2 + o0]));
            const float hk[4] = {hv.x, hv.y, hv.z, hv.w};
            const float wo[4] = {wv.x, wv.y, wv.z, wv.w};
            #pragma unroll
            for (int i = 0; i < 4; ++i)
                #pragma unroll
                for (int j = 0; j < 4; ++j)
                    acc[i][j] = fmaf(wo[i], hk[j], acc[i][j]);
        }

        #pragma unroll
        for (int i = 0; i < 4; ++i) {
            float4 v;
            v.x = fmaxf(acc[i][0], 0.f);
            v.y = fmaxf(acc[i][1], 0.f);
            v.z = fmaxf(acc[i][2], 0.f);
            v.w = fmaxf(acc[i][3], 0.f);
            *reinterpret_cast<float4*>(&h2T[(o0 + i) * KNN + k0]) = v;
        }
    }
    __syncthreads();

    // ---- layer 3: 128 -> 256 + max over k, 4o x 8k register tile ----------
    // 32 FFMA per (2x LDS.128 + 1x LDG.128)  ->  ~10.7 FFMA/load.
    {
        const int ot = t >> 2;           // 64 o-tiles
        const int o0 = ot * 4;
        const int kt = t & 3;            // 4 k-tiles of 8
        const int k0 = kt * 8;

        float acc[4][8];
        #pragma unroll
        for (int i = 0; i < 4; ++i)
            #pragma unroll
            for (int j = 0; j < 8; ++j)
                acc[i][j] = 0.f;

        #pragma unroll 4
        for (int c = 0; c < C2; ++c) {
            const float4 ha = *reinterpret_cast<const float4*>(&h2T[c * KNN + k0]);
            const float4 hb = *reinterpret_cast<const float4*>(&h2T[c * KNN + k0 + 4]);
            const float4 wv = __ldg(reinterpret_cast<const float4*>(&g_W3T[c * EMB + o0]));
            const float hk[8] = {ha.x, ha.y, ha.z, ha.w, hb.x, hb.y, hb.z, hb.w};
            const float wo[4] = {wv.x, wv.y, wv.z, wv.w};
            #pragma unroll
            for (int i = 0; i < 4; ++i)
                #pragma unroll
                for (int j = 0; j < 8; ++j)
                    acc[i][j] = fmaf(wo[i], hk[j], acc[i][j]);
        }

        // max over this thread's 8 k, then butterfly over the 4 lanes (same
        // warp: lanes differ only in bits 0..1) holding the other k-tiles.
        float m[4];
        #pragma unroll
        for (int i = 0; i < 4; ++i) {
            float v = acc[i][0];
            #pragma unroll
            for (int j = 1; j < 8; ++j) v = fmaxf(v, acc[i][j]);
            v = fmaxf(v, __shfl_xor_sync(0xffffffffu, v, 1));
            v = fmaxf(v, __shfl_xor_sync(0xffffffffu, v, 2));
            m[i] = v;
        }

        if (kt == 0) {
            const float4 bv = *reinterpret_cast<const float4*>(&b3[o0]);
            float4 r;
            r.x = m[0] + bv.x;
            r.y = m[1] + bv.y;
            r.z = m[2] + bv.z;
            r.w = m[3] + bv.w;
            *reinterpret_cast<float4*>(&out[(size_t)bm * EMB + o0]) = r;
        }
    }
}

extern "C" void kernel_launch(void* const* d_in, const int* in_sizes, int n_in,
                              void* d_out, int out_size)
{
    // metadata order: xyz, centers, idx_knn, W1, b1, W2, b2, W3, b3
    const float* xyz     = (const float*)d_in[0];
    const float* centers = (const float*)d_in[1];
    const int*   idx_knn = (const int*)  d_in[2];
    const float* W1      = (const float*)d_in[3];
    const float* b1      = (const float*)d_in[4];
    const float* W2      = (const float*)d_in[5];
    const float* b2      = (const float*)d_in[6];
    const float* W3      = (const float*)d_in[7];
    const float* b3      = (const float*)d_in[8];
    float* out = (float*)d_out;

    const int prep_elems = C1 * C2 + C2 * EMB;   // 40960
    prep_transpose<<<(prep_elems + 255) / 256, 256>>>(W2, W3);
    patch_embed_kernel<<<Bn * MC, 256>>>(
        xyz, centers, idx_knn, W1, b1, b2, b3, out);
}

// round 5
// speedup vs baseline: 6.5716x; 3.5828x over previous
#include <cuda_runtime.h>
#include <cstdint>

// ============================ problem constants ============================
#define Bn      8
#define Np      16384
#define MCc     2048
#define KNNk    32
#define EMBc    256
#define MT      2                 // m-tiles per group
#define NGROUPS (Bn * MCc / MT)   // 8192
#define GRID    148
#define NT      256

// SMEM layout in floats. Strides padded so (stride mod 8) == 4:
// fragment loads hit banks (4*gp + tg) -> conflict-free.
#define PK1 68                    // K=64  + 4
#define PK2 132                   // K=128 + 4
#define S_W2 0                    // [128][68]
#define S_W3 (S_W2 + 128 * PK1)   // [256][132]
#define S_H  (S_W3 + 256 * PK2)   // [64][132] h2 (h1 aliased, stride 68)
#define S_B2 (S_H + 64 * PK2)     // 128
#define S_W1 (S_B2 + 128)         // 192
#define S_B1 (S_W1 + 192)         // 64
#define S_TOT (S_B1 + 64)
#define SMEM_BYTES (S_TOT * 4)    // 205312 B

// ============================ PTX helpers ============================
__device__ __forceinline__ uint32_t cvt_tf32(float f) {
    uint32_t r;
    asm("cvt.rna.tf32.f32 %0, %1;" : "=r"(r) : "f"(f));
    return r;
}

// D = A*B + D,  m16n8k8, A row-major tf32, B col-major tf32, fp32 accum.
__device__ __forceinline__ void mma8(float* d,
                                     const uint32_t* a,
                                     uint32_t b0, uint32_t b1) {
    asm volatile(
        "mma.sync.aligned.m16n8k8.row.col.f32.tf32.tf32.f32 "
        "{%0,%1,%2,%3}, {%4,%5,%6,%7}, {%8,%9}, {%0,%1,%2,%3};"
        : "+f"(d[0]), "+f"(d[1]), "+f"(d[2]), "+f"(d[3])
        : "r"(a[0]), "r"(a[1]), "r"(a[2]), "r"(a[3]), "r"(b0), "r"(b1));
}

// ============================ kernel ============================
__global__ __launch_bounds__(NT, 1)
void patch_embed_mma(const float* __restrict__ xyz,
                     const float* __restrict__ centers,
                     const int*   __restrict__ idx_knn,
                     const float* __restrict__ W1,
                     const float* __restrict__ b1,
                     const float* __restrict__ W2,
                     const float* __restrict__ b2,
                     const float* __restrict__ W3,
                     const float* __restrict__ b3,
                     float*       __restrict__ out)
{
    extern __shared__ __align__(16) float sm[];
    uint32_t* sW2u = reinterpret_cast<uint32_t*>(sm + S_W2);
    uint32_t* sW3u = reinterpret_cast<uint32_t*>(sm + S_W3);
    uint32_t* sHu  = reinterpret_cast<uint32_t*>(sm + S_H);
    float*    sB2  = sm + S_B2;
    float*    sW1v = sm + S_W1;
    float*    sB1v = sm + S_B1;

    const int tid  = threadIdx.x;
    const int wid  = tid >> 5;
    const int lane = tid & 31;
    const int gp   = lane >> 2;   // groupID   (fragment row/col group)
    const int tg   = lane & 3;    // threadID_in_group

    // warp tiling: mtp = which 32-row half (== m_local), nq = n quarter
    const int mtp = wid & 1;
    const int nq  = wid >> 1;

    // ---- one-time staging (tf32-rounded weights) ---------------------------
    for (int i = tid; i < 128 * 64; i += NT) {        // W2 [n=128][k=64]
        int n = i >> 6, k = i & 63;
        sW2u[n * PK1 + k] = cvt_tf32(W2[i]);
    }
    for (int i = tid; i < 256 * 128; i += NT) {       // W3 [n=256][k=128]
        int n = i >> 7, k = i & 127;
        sW3u[n * PK2 + k] = cvt_tf32(W3[i]);
    }
    if (tid < 192) sW1v[tid] = W1[tid];
    if (tid < 64)  sB1v[tid] = b1[tid];
    if (tid < 128) sB2[tid]  = b2[tid];
    __syncthreads();

    for (int g = blockIdx.x; g < NGROUPS; g += GRID) {
        const int bm0 = g * MT;

        // ---- layer 1: gather + 3->64 relu -> h1 (stride PK1, aliased in sH)
        {
            const int row = tid & 63;                 // m_local*32 + k
            const int cb  = (tid >> 6) * 16;          // 16-channel block
            const int bm  = bm0 + (row >> 5);
            const int kk  = row & 31;
            const int ii  = __ldg(&idx_knn[bm * KNNk + kk]);
            const float* p = xyz + ((size_t)(bm >> 11) * Np + ii) * 3;
            const float x = p[0] - __ldg(&centers[bm * 3 + 0]);
            const float y = p[1] - __ldg(&centers[bm * 3 + 1]);
            const float z = p[2] - __ldg(&centers[bm * 3 + 2]);

            uint32_t hv[16];
            #pragma unroll
            for (int o = 0; o < 16; ++o) {
                const int oo = cb + o;
                float v = sB1v[oo];
                v = fmaf(sW1v[oo * 3 + 0], x, v);
                v = fmaf(sW1v[oo * 3 + 1], y, v);
                v = fmaf(sW1v[oo * 3 + 2], z, v);
                hv[o] = cvt_tf32(fmaxf(v, 0.f));
            }
            uint32_t* h1r = sHu + row * PK1 + cb;     // 16B-aligned
            #pragma unroll
            for (int j = 0; j < 4; ++j)
                *reinterpret_cast<uint4*>(h1r + 4 * j) =
                    make_uint4(hv[4*j], hv[4*j+1], hv[4*j+2], hv[4*j+3]);
        }
        __syncthreads();

        // ---- GEMM1: D1[64x128] = h1[64x64] * W2^T ------------------------
        // warp: 2 m16-tiles (rows 32*mtp + {0,16}+...) x 4 n-tiles (nq*32..)
        float acc1[2][4][4];
        #pragma unroll
        for (int m = 0; m < 2; ++m)
            #pragma unroll
            for (int nt = 0; nt < 4; ++nt)
                #pragma unroll
                for (int j = 0; j < 4; ++j) acc1[m][nt][j] = 0.f;

        #pragma unroll
        for (int ks = 0; ks < 8; ++ks) {
            const int k0 = ks * 8;
            uint32_t a[2][4];
            #pragma unroll
            for (int m = 0; m < 2; ++m) {
                const uint32_t* hr = sHu + (mtp*32 + m*16 + gp) * PK1 + k0 + tg;
                a[m][0] = hr[0];
                a[m][1] = hr[8 * PK1];
                a[m][2] = hr[4];
                a[m][3] = hr[8 * PK1 + 4];
            }
            #pragma unroll
            for (int nt = 0; nt < 4; ++nt) {
                const uint32_t* wr = sW2u + (nq*32 + nt*8 + gp) * PK1 + k0 + tg;
                const uint32_t b0v = wr[0], b1v = wr[4];
                mma8(acc1[0][nt], a[0], b0v, b1v);
                mma8(acc1[1][nt], a[1], b0v, b1v);
            }
        }
        __syncthreads();   // everyone done reading h1 before h2 overwrites it

        // ---- epilogue 1: h2 = tf32(relu(D1 + b2)), stride PK2 -------------
        #pragma unroll
        for (int m = 0; m < 2; ++m) {
            const int r0 = mtp*32 + m*16 + gp;
            #pragma unroll
            for (int nt = 0; nt < 4; ++nt) {
                const int c0 = nq*32 + nt*8 + 2*tg;
                const float bb0 = sB2[c0], bb1 = sB2[c0 + 1];
                uint2 lo, hi;
                lo.x = cvt_tf32(fmaxf(acc1[m][nt][0] + bb0, 0.f));
                lo.y = cvt_tf32(fmaxf(acc1[m][nt][1] + bb1, 0.f));
                hi.x = cvt_tf32(fmaxf(acc1[m][nt][2] + bb0, 0.f));
                hi.y = cvt_tf32(fmaxf(acc1[m][nt][3] + bb1, 0.f));
                *reinterpret_cast<uint2*>(sHu + r0 * PK2 + c0)       = lo;
                *reinterpret_cast<uint2*>(sHu + (r0 + 8) * PK2 + c0) = hi;
            }
        }
        __syncthreads();

        // ---- GEMM2: D2[64x256] = h2[64x128] * W3^T ------------------------
        // warp: 2 m16-tiles (one m_local) x 8 n-tiles (nq*64..)
        float acc2[2][8][4];
        #pragma unroll
        for (int m = 0; m < 2; ++m)
            #pragma unroll
            for (int nt = 0; nt < 8; ++nt)
                #pragma unroll
                for (int j = 0; j < 4; ++j) acc2[m][nt][j] = 0.f;

        #pragma unroll
        for (int ks = 0; ks < 16; ++ks) {
            const int k0 = ks * 8;
            uint32_t a[2][4];
            #pragma unroll
            for (int m = 0; m < 2; ++m) {
                const uint32_t* hr = sHu + (mtp*32 + m*16 + gp) * PK2 + k0 + tg;
                a[m][0] = hr[0];
                a[m][1] = hr[8 * PK2];
                a[m][2] = hr[4];
                a[m][3] = hr[8 * PK2 + 4];
            }
            #pragma unroll
            for (int nt = 0; nt < 8; ++nt) {
                const uint32_t* wr = sW3u + (nq*64 + nt*8 + gp) * PK2 + k0 + tg;
                const uint32_t b0v = wr[0], b1v = wr[4];
                mma8(acc2[0][nt], a[0], b0v, b1v);
                mma8(acc2[1][nt], a[1], b0v, b1v);
            }
        }

        // ---- max over k (32 rows of this warp's m_local) + b3 + store -----
        // Thread holds rows {gp, gp+8, gp+16, gp+24} per column; butterfly
        // over gp (xor 4,8,16) completes the 32-row max.
        const int bm = bm0 + mtp;
        #pragma unroll
        for (int nt = 0; nt < 8; ++nt) {
            float m0 = fmaxf(fmaxf(acc2[0][nt][0], acc2[0][nt][2]),
                             fmaxf(acc2[1][nt][0], acc2[1][nt][2]));
            float m1 = fmaxf(fmaxf(acc2[0][nt][1], acc2[0][nt][3]),
                             fmaxf(acc2[1][nt][1], acc2[1][nt][3]));
            #pragma unroll
            for (int s = 4; s < 32; s <<= 1) {
                m0 = fmaxf(m0, __shfl_xor_sync(0xffffffffu, m0, s));
                m1 = fmaxf(m1, __shfl_xor_sync(0xffffffffu, m1, s));
            }
            if (lane < 4) {
                const int c = nq*64 + nt*8 + 2*tg;
                float2 r2;
                r2.x = m0 + __ldg(&b3[c]);
                r2.y = m1 + __ldg(&b3[c + 1]);
                *reinterpret_cast<float2*>(&out[(size_t)bm * EMBc + c]) = r2;
            }
        }
        __syncthreads();   // GEMM2 reads of sH done before next layer-1 write
    }
}

// ============================ launch ============================
extern "C" void kernel_launch(void* const* d_in, const int* in_sizes, int n_in,
                              void* d_out, int out_size)
{
    // metadata order: xyz, centers, idx_knn, W1, b1, W2, b2, W3, b3
    const float* xyz     = (const float*)d_in[0];
    const float* centers = (const float*)d_in[1];
    const int*   idx_knn = (const int*)  d_in[2];
    const float* W1      = (const float*)d_in[3];
    const float* b1      = (const float*)d_in[4];
    const float* W2      = (const float*)d_in[5];
    const float* b2      = (const float*)d_in[6];
    const float* W3      = (const float*)d_in[7];
    const float* b3      = (const float*)d_in[8];
    float* out = (float*)d_out;

    // Idempotent attribute set (not a stream op; capture-safe, no allocation).
    cudaFuncSetAttribute(patch_embed_mma,
                         cudaFuncAttributeMaxDynamicSharedMemorySize,
                         SMEM_BYTES);

    patch_embed_mma<<<GRID, NT, SMEM_BYTES>>>(
        xyz, centers, idx_knn, W1, b1, W2, b2, W3, b3, out);
}